// round 14
// baseline (speedup 1.0000x reference)
#include <cuda_runtime.h>
#include <cuda_fp16.h>
#include <cstdint>
#include <cstddef>

#define HD 1024
#define NB 128
#define NS 128
#define NROW (NB*NS)
#define NCTA_SCAN 256
#define TILE_B 16384            // 128 rows x 64 fp16 (128B/row), swizzled
#define TILE_S 8192             // 64 rows x 64 fp16
#define GEMM_SMEM (6*TILE_B)    // 98304: 3xA + 3xB (2 CTAs/SM)
#define SCAN_SMEM (2*TILE_B + 2*TILE_S)  // 49152 (2 CTAs/SM)

// ---------------- scratch ----------------
__device__ __align__(16) unsigned g_FRh[(size_t)NS*NB*HD/2];
__device__ __align__(16) unsigned g_FWh[(size_t)NS*NB*HD/2];
__device__ __align__(16) unsigned g_Ch[NB*HD/2];
__device__ __align__(16) float g_Otmp[NB*HD];
__device__ __align__(16) unsigned g_parth[(size_t)NCTA_SCAN*4096];  // 128x64 fp16 per CTA
__device__ __align__(16) float g_Glogit[NROW];
__device__ __align__(16) float g_Gt[NS*NB];
__device__ __align__(16) unsigned g_fh[(size_t)NB*NS*HD/2];
__device__ __align__(16) unsigned g_zh[(size_t)NROW*4*HD/2];
__device__ __align__(16) unsigned g_Wz1h[(size_t)HD*4*HD/2];
__device__ __align__(16) unsigned g_Wrh[(size_t)HD*HD/2];
__device__ __align__(16) unsigned g_Wh[(size_t)HD*HD/2];
__device__ __align__(16) unsigned g_Urh[(size_t)HD*HD/2];
__device__ __align__(16) unsigned g_Uh[(size_t)HD*HD/2];
__device__ __align__(16) unsigned g_Wmh[(size_t)HD*3*HD/2];
__device__ __align__(16) unsigned g_pmh[NB*HD/2];
__device__ __align__(16) unsigned g_qh[NB*HD/2];
__device__ __align__(16) unsigned g_flags[NCTA_SCAN*32];

// ---------------- helpers ----------------
__device__ __forceinline__ unsigned pack_h2(float x, float y){
    __half2 h = __floats2half2_rn(x, y);
    return *reinterpret_cast<unsigned*>(&h);
}
__device__ __forceinline__ float2 h2f2(unsigned u){
    return __half22float2(*reinterpret_cast<const __half2*>(&u));
}
__device__ __forceinline__ uint32_t smem_u32(const void* p){
    uint32_t a; asm("{ .reg .u64 t; cvta.to.shared.u64 t, %1; cvt.u32.u64 %0, t; }"
                    : "=r"(a) : "l"(p)); return a;
}
__device__ __forceinline__ void cpa16(uint32_t dst, const void* src){
    asm volatile("cp.async.cg.shared.global [%0], [%1], 16;" :: "r"(dst), "l"(src));
}
#define CP_COMMIT() asm volatile("cp.async.commit_group;" ::: "memory")
#define CP_WAIT(n)  asm volatile("cp.async.wait_group %0;" :: "n"(n) : "memory")

__device__ __forceinline__ unsigned ldcg_u32(const unsigned* p){
    unsigned v; asm volatile("ld.global.cg.u32 %0, [%1];" : "=r"(v) : "l"(p)); return v;
}
__device__ __forceinline__ void stcg_u32(unsigned* p, unsigned v){
    asm volatile("st.global.cg.u32 [%0], %1;" :: "l"(p), "r"(v) : "memory");
}
__device__ __forceinline__ void ldsm4(unsigned* r, uint32_t addr){
    asm volatile("ldmatrix.sync.aligned.m8n8.x4.shared.b16 {%0,%1,%2,%3}, [%4];"
        : "=r"(r[0]),"=r"(r[1]),"=r"(r[2]),"=r"(r[3]) : "r"(addr));
}
__device__ __forceinline__ void mma16(float* d, const unsigned* a, const unsigned* b){
    asm volatile("mma.sync.aligned.m16n8k16.row.col.f32.f16.f16.f32 "
        "{%0,%1,%2,%3},{%4,%5,%6,%7},{%8,%9},{%0,%1,%2,%3};\n"
        : "+f"(d[0]),"+f"(d[1]),"+f"(d[2]),"+f"(d[3])
        : "r"(a[0]),"r"(a[1]),"r"(a[2]),"r"(a[3]),"r"(b[0]),"r"(b[1]));
}

__device__ __forceinline__ void compute64h(uint32_t aBase, uint32_t bBase,
        const uint32_t* RA, const uint32_t* RB, const uint32_t* TA, const uint32_t* TB,
        float acc[2][8][4]){
    #pragma unroll
    for (int ks = 0; ks < 4; ks++){
        unsigned a0[4], a1[4], bb[4][4];
        ldsm4(a0, aBase + RA[0] + TA[ks]);
        ldsm4(a1, aBase + RA[1] + TA[ks]);
        #pragma unroll
        for (int p = 0; p < 4; p++) ldsm4(bb[p], bBase + RB[p] + TB[ks]);
        #pragma unroll
        for (int mi = 0; mi < 2; mi++){
            const unsigned* a = mi ? a1 : a0;
            #pragma unroll
            for (int p = 0; p < 4; p++){
                unsigned bl[2] = {bb[p][0], bb[p][1]};
                unsigned bh[2] = {bb[p][2], bb[p][3]};
                mma16(acc[mi][2*p],   a, bl);
                mma16(acc[mi][2*p+1], a, bh);
            }
        }
    }
}

__device__ __forceinline__ void compute64h64(uint32_t aBase, uint32_t bBase,
        const uint32_t* RA, const uint32_t* RB, const uint32_t* TA, const uint32_t* TB,
        float acc[2][4][4]){
    #pragma unroll
    for (int ks = 0; ks < 4; ks++){
        unsigned a0[4], a1[4], bb[2][4];
        ldsm4(a0, aBase + RA[0] + TA[ks]);
        ldsm4(a1, aBase + RA[1] + TA[ks]);
        #pragma unroll
        for (int p = 0; p < 2; p++) ldsm4(bb[p], bBase + RB[p] + TB[ks]);
        #pragma unroll
        for (int mi = 0; mi < 2; mi++){
            const unsigned* a = mi ? a1 : a0;
            #pragma unroll
            for (int p = 0; p < 2; p++){
                unsigned bl[2] = {bb[p][0], bb[p][1]};
                unsigned bh[2] = {bb[p][2], bb[p][3]};
                mma16(acc[mi][2*p],   a, bl);
                mma16(acc[mi][2*p+1], a, bh);
            }
        }
    }
}

#define LDSM_OFFSETS_H() \
    int rowA = warp_m + (lane & 15); \
    uint32_t RA[2] = { (uint32_t)rowA*128u, (uint32_t)(rowA+16)*128u }; \
    uint32_t RB[4]; \
    _Pragma("unroll") for (int p_ = 0; p_ < 4; p_++) \
        RB[p_] = (uint32_t)(warp_n + p_*16 + (lane & 7) + ((lane >> 4) & 1)*8)*128u; \
    uint32_t TA[4], TB[4]; \
    _Pragma("unroll") for (int k_ = 0; k_ < 4; k_++){ \
        TA[k_] = (uint32_t)(((k_*2 + (lane >> 4)) ^ (rowA & 7))*16); \
        TB[k_] = (uint32_t)(((k_*2 + ((lane >> 3) & 1)) ^ (lane & 7))*16); }

#define LDSM_OFFSETS_H64() \
    int rowA = warp_m + (lane & 15); \
    uint32_t RA[2] = { (uint32_t)rowA*128u, (uint32_t)(rowA+16)*128u }; \
    uint32_t RB[2]; \
    _Pragma("unroll") for (int p_ = 0; p_ < 2; p_++) \
        RB[p_] = (uint32_t)(warp_n + p_*16 + (lane & 7) + ((lane >> 4) & 1)*8)*128u; \
    uint32_t TA[4], TB[4]; \
    _Pragma("unroll") for (int k_ = 0; k_ < 4; k_++){ \
        TA[k_] = (uint32_t)(((k_*2 + (lane >> 4)) ^ (rowA & 7))*16); \
        TB[k_] = (uint32_t)(((k_*2 + ((lane >> 3) & 1)) ^ (lane & 7))*16); }

#define ZERO_ACC(acc) { \
    _Pragma("unroll") for (int _i=0;_i<2;_i++) \
    _Pragma("unroll") for (int _j=0;_j<8;_j++) \
    _Pragma("unroll") for (int _k=0;_k<4;_k++) acc[_i][_j][_k]=0.f; }
#define ZERO_ACC4(acc) { \
    _Pragma("unroll") for (int _i=0;_i<2;_i++) \
    _Pragma("unroll") for (int _j=0;_j<4;_j++) \
    _Pragma("unroll") for (int _k=0;_k<4;_k++) acc[_i][_j][_k]=0.f; }

#define GEMM_CPH(i_, st_, Ab_, AldB_, Bb_, BldB_) { \
    size_t kb_ = (size_t)(i_)*128; \
    _Pragma("unroll") for (int j = 0; j < 4; j++){ int r_ = rb + j*32; \
        cpa16(sbase + (st_)*TILE_B + r_*128 + swz16, \
              (Ab_) + (size_t)r_*(AldB_) + kb_ + u16); \
        cpa16(sbase + (3 + (st_))*TILE_B + r_*128 + swz16, \
              (Bb_) + (size_t)r_*(BldB_) + kb_ + u16); } CP_COMMIT(); }

// ---------------- K0: per-replay init ----------------
__global__ void k_init(){
    int i = blockIdx.x * blockDim.x + threadIdx.x;
    if (i < NCTA_SCAN*32) g_flags[i] = 0u;
    if (i < NROW) g_Glogit[i] = 0.f;
    if (i < NB*HD/2) g_Ch[i] = 0u;
    if (i < NB*HD) g_Otmp[i] = 0.f;
}

// ---------------- Kc: fp32 -> fp16 bulk convert (1/2/4-way batched) ----------------
__global__ void k_cvt_h(const float4* __restrict__ src, uint2* __restrict__ dst, int n4){
    for (int i = blockIdx.x*blockDim.x + threadIdx.x; i < n4; i += gridDim.x*blockDim.x){
        float4 v = src[i];
        dst[i] = make_uint2(pack_h2(v.x, v.y), pack_h2(v.z, v.w));
    }
}
__global__ void k_cvt4(const float4* __restrict__ s0, const float4* __restrict__ s1,
                       const float4* __restrict__ s2, const float4* __restrict__ s3,
                       uint2* d0, uint2* d1, uint2* d2, uint2* d3, int n4){
    int w = blockIdx.y;
    const float4* src = (w == 0) ? s0 : (w == 1) ? s1 : (w == 2) ? s2 : s3;
    uint2* dst = (w == 0) ? d0 : (w == 1) ? d1 : (w == 2) ? d2 : d3;
    for (int i = blockIdx.x*blockDim.x + threadIdx.x; i < n4; i += gridDim.x*blockDim.x){
        float4 v = src[i];
        dst[i] = make_uint2(pack_h2(v.x, v.y), pack_h2(v.z, v.w));
    }
}

// ---------------- Kz: build z (fp16) + facts fp16 ----------------
__global__ void k_zb_h(const float* __restrict__ facts, const float* __restrict__ q,
                       const float* __restrict__ pm){
    int row = blockIdx.x;
    int bt = row >> 7;
    int t = threadIdx.x;
    float4 f  = *reinterpret_cast<const float4*>(facts + (size_t)row*HD + t*4);
    float4 qv = *reinterpret_cast<const float4*>(q  + (size_t)bt*HD + t*4);
    float4 mv = *reinterpret_cast<const float4*>(pm + (size_t)bt*HD + t*4);
    char* zr = reinterpret_cast<char*>(g_zh) + (size_t)row*8192;
    *reinterpret_cast<uint2*>(reinterpret_cast<char*>(g_fh) + (size_t)row*2048 + t*8) =
        make_uint2(pack_h2(f.x, f.y), pack_h2(f.z, f.w));
    *reinterpret_cast<uint2*>(zr + 0*2048 + t*8) =
        make_uint2(pack_h2(f.x*qv.x, f.y*qv.y), pack_h2(f.z*qv.z, f.w*qv.w));
    *reinterpret_cast<uint2*>(zr + 1*2048 + t*8) =
        make_uint2(pack_h2(f.x*mv.x, f.y*mv.y), pack_h2(f.z*mv.z, f.w*mv.w));
    *reinterpret_cast<uint2*>(zr + 2*2048 + t*8) =
        make_uint2(pack_h2(fabsf(f.x-qv.x), fabsf(f.y-qv.y)), pack_h2(fabsf(f.z-qv.z), fabsf(f.w-qv.w)));
    *reinterpret_cast<uint2*>(zr + 3*2048 + t*8) =
        make_uint2(pack_h2(fabsf(f.x-mv.x), fabsf(f.y-mv.y)), pack_h2(fabsf(f.z-mv.z), fabsf(f.w-mv.w)));
}

// ================= K1: G logits =================
__global__ void __launch_bounds__(256,2) kD_G(
        const float* __restrict__ bz1, const float* __restrict__ Wz2){
    extern __shared__ unsigned us[];
    uint32_t sbase = smem_u32(us);
    int tid = threadIdx.x, wid = tid >> 5, lane = tid & 31;
    int lg = lane >> 2, lk = lane & 3;
    int warp_m = (wid >> 1) * 32, warp_n = (wid & 1) * 64;
    int nt = blockIdx.x, bt = blockIdx.y;
    int u16 = (tid & 7) * 16, rb = tid >> 3;
    uint32_t swz16 = (uint32_t)(((tid & 7) ^ (rb & 7)) * 16);
    LDSM_OFFSETS_H();
    const char* Ab = reinterpret_cast<const char*>(g_zh) + (size_t)bt*NS*8192;
    const char* Bb = reinterpret_cast<const char*>(g_Wz1h) + (size_t)(nt*128)*8192;
    float acc[2][8][4]; ZERO_ACC(acc);

    const int NBLK = 64;
    GEMM_CPH(0, 0, Ab, 8192, Bb, 8192);
    GEMM_CPH(1, 1, Ab, 8192, Bb, 8192);
    int st = 0;
    for (int i = 0; i < NBLK; i++){
        CP_WAIT(1);
        __syncthreads();
        if (i + 2 < NBLK){
            int st2 = st + 2; if (st2 >= 3) st2 -= 3;
            GEMM_CPH(i+2, st2, Ab, 8192, Bb, 8192);
        }
        compute64h(sbase + st*TILE_B, sbase + (3+st)*TILE_B, RA, RB, TA, TB, acc);
        if (++st == 3) st = 0;
    }

    float rs[4] = {0.f, 0.f, 0.f, 0.f};
    #pragma unroll
    for (int mi = 0; mi < 2; mi++)
        #pragma unroll
        for (int ni = 0; ni < 8; ni++){
            int c0 = nt*128 + warp_n + ni*8 + lk*2;
            float w0 = Wz2[c0], w1 = Wz2[c0+1];
            float z0 = bz1[c0], z1 = bz1[c0+1];
            rs[mi*2+0] += tanhf(acc[mi][ni][0]+z0)*w0 + tanhf(acc[mi][ni][1]+z1)*w1;
            rs[mi*2+1] += tanhf(acc[mi][ni][2]+z0)*w0 + tanhf(acc[mi][ni][3]+z1)*w1;
        }
    #pragma unroll
    for (int r = 0; r < 4; r++){
        rs[r] += __shfl_xor_sync(0xffffffffu, rs[r], 1);
        rs[r] += __shfl_xor_sync(0xffffffffu, rs[r], 2);
    }
    if (lk == 0){
        int s0 = warp_m + lg;
        atomicAdd(&g_Glogit[bt*NS + s0     ], rs[0]);
        atomicAdd(&g_Glogit[bt*NS + s0 + 8 ], rs[1]);
        atomicAdd(&g_Glogit[bt*NS + s0 + 16], rs[2]);
        atomicAdd(&g_Glogit[bt*NS + s0 + 24], rs[3]);
    }
}

// ================= K3: FR/FW (fp16 outputs) =================
__global__ void __launch_bounds__(256,2) kD_F(
        const float* __restrict__ br, const float* __restrict__ bw){
    extern __shared__ unsigned us[];
    uint32_t sbase = smem_u32(us);
    int tid = threadIdx.x, wid = tid >> 5, lane = tid & 31;
    int lg = lane >> 2, lk = lane & 3;
    int warp_m = (wid >> 1) * 32, warp_n = (wid & 1) * 64;
    int nt = blockIdx.x, bt = blockIdx.y, which = blockIdx.z;
    const unsigned* Wsel = which ? g_Wh : g_Wrh;
    const float*    bsel = which ? bw : br;
    unsigned* Outh = which ? g_FWh : g_FRh;
    int u16 = (tid & 7) * 16, rb = tid >> 3;
    uint32_t swz16 = (uint32_t)(((tid & 7) ^ (rb & 7)) * 16);
    LDSM_OFFSETS_H();
    const char* Ab = reinterpret_cast<const char*>(g_fh) + (size_t)bt*NS*2048;
    const char* Bb = reinterpret_cast<const char*>(Wsel) + (size_t)(nt*128)*2048;
    float acc[2][8][4]; ZERO_ACC(acc);

    const int NBLK = 16;
    GEMM_CPH(0, 0, Ab, 2048, Bb, 2048);
    GEMM_CPH(1, 1, Ab, 2048, Bb, 2048);
    int st = 0;
    for (int i = 0; i < NBLK; i++){
        CP_WAIT(1);
        __syncthreads();
        if (i + 2 < NBLK){
            int st2 = st + 2; if (st2 >= 3) st2 -= 3;
            GEMM_CPH(i+2, st2, Ab, 2048, Bb, 2048);
        }
        compute64h(sbase + st*TILE_B, sbase + (3+st)*TILE_B, RA, RB, TA, TB, acc);
        if (++st == 3) st = 0;
    }

    #pragma unroll
    for (int mi = 0; mi < 2; mi++){
        int r0 = warp_m + mi*16 + lg;
        #pragma unroll
        for (int ni = 0; ni < 8; ni++){
            int h = nt*128 + warp_n + ni*8 + lk*2;
            float b0 = bsel[h], b1 = bsel[h+1];
            Outh[((size_t)r0*(NB*HD) + (size_t)bt*HD + h) >> 1] =
                pack_h2(acc[mi][ni][0]+b0, acc[mi][ni][1]+b1);
            Outh[((size_t)(r0+8)*(NB*HD) + (size_t)bt*HD + h) >> 1] =
                pack_h2(acc[mi][ni][2]+b0, acc[mi][ni][3]+b1);
        }
    }
}

// ---------------- K2: softmax ----------------
__global__ void k_softmax(){
    int bt = blockIdx.x, t = threadIdx.x;
    float v = g_Glogit[bt*NS + t];
    __shared__ float sm_[4], ss[4];
    float mx = v;
    #pragma unroll
    for (int o = 16; o; o >>= 1) mx = fmaxf(mx, __shfl_xor_sync(0xffffffffu, mx, o));
    if ((t & 31) == 0) sm_[t >> 5] = mx;
    __syncthreads();
    mx = fmaxf(fmaxf(sm_[0], sm_[1]), fmaxf(sm_[2], sm_[3]));
    float e = __expf(v - mx);
    float sum = e;
    #pragma unroll
    for (int o = 16; o; o >>= 1) sum += __shfl_xor_sync(0xffffffffu, sum, o);
    if ((t & 31) == 0) ss[t >> 5] = sum;
    __syncthreads();
    sum = ss[0] + ss[1] + ss[2] + ss[3];
    g_Gt[t*NB + bt] = e / sum;
}

// ---------------- K4: persistent scan (256 CTAs, 2/SM, 8-way K-split) ----------------
__device__ __forceinline__ void gsync(unsigned step, int tid, int cta){
    __syncthreads();
    if (tid == 0){
        __threadfence();
        stcg_u32(&g_flags[cta*32], step);
    }
    // all 256 threads each poll one of the 256 CTA flags
    while (ldcg_u32(&g_flags[tid*32]) < step) { }
    __threadfence();
    __syncthreads();
}
__device__ __forceinline__ float gru_upd(float fr, float fw, float y1, float y2,
                                         float b_ur, float b_u, float c, float g){
    float r  = 1.f / (1.f + __expf(-(fr + y1 + b_ur)));
    float ht = tanhf(fw + r * (y2 + b_u));
    return g * ht + (1.f - g) * c;
}

__global__ void __launch_bounds__(256,2) kD_scan(
        const float* __restrict__ bur, const float* __restrict__ bu){
    extern __shared__ unsigned us[];   // A tiles 0-1 (128x64); B resident tiles (64x64) at 2*TILE_B
    uint32_t sbase = smem_u32(us);
    int cta = blockIdx.x, tid = threadIdx.x;
    int wid = tid >> 5, lane = tid & 31, lg = lane >> 2, lk = lane & 3;
    int warp_m = (wid & 3) * 32, warp_n = (wid >> 2) * 32;
    int u16 = (tid & 7) * 16, rb = tid >> 3;
    uint32_t swz16 = (uint32_t)(((tid & 7) ^ (rb & 7)) * 16);
    LDSM_OFFSETS_H64();
    int nt  = cta >> 3;             // 0..31: 0-15 Y1 (Ur), 16-31 Y2 (U)
    int knt = cta & 7;              // K-slice of 128 fp16
    const unsigned* Wsel = (nt < 16) ? g_Urh : g_Uh;
    int nbase = (nt & 15) * 64;
    unsigned* P = g_parth + (size_t)cta * 4096;   // 128x64 fp16
    const char* Wb = reinterpret_cast<const char*>(Wsel) + (size_t)nbase*2048 + knt*256;
    const char* Cb = reinterpret_cast<const char*>(g_Ch) + knt*256;
    uint32_t bBase0 = sbase + 2*TILE_B;

    // resident weights: 64 rows x 128 fp16 = 2 sub-tiles of 64x64
    #pragma unroll
    for (int j = 0; j < 4; j++){
        int c = j >> 1, n = rb + (j & 1)*32;
        cpa16(bBase0 + c*TILE_S + n*128 + swz16,
              Wb + (size_t)n*2048 + c*128 + u16);
    }
    CP_COMMIT();
    CP_WAIT(0);
    __syncthreads();

    int e  = (cta*256 + tid) * 2;   // 2 consecutive h per thread (one half2)
    int eb = e >> 10, eh = e & (HD-1);
    int nt1 = eh >> 6, hm = eh & 63;
    float2 vur = *reinterpret_cast<const float2*>(bur + eh);
    float2 vu  = *reinterpret_cast<const float2*>(bu + eh);
    float2 creg = make_float2(0.f, 0.f);

    unsigned bar = 0;
    for (int s = 0; s < NS; s++){
        unsigned fru = g_FRh[(((size_t)s*NB + eb)*HD + eh) >> 1];
        unsigned fwu = g_FWh[(((size_t)s*NB + eb)*HD + eh) >> 1];
        float gg = g_Gt[s*NB + eb];

        // phase A: C slice 128x128 fp16 as 2 sub-tiles of 128x64
        #pragma unroll
        for (int c = 0; c < 2; c++){
            #pragma unroll
            for (int j = 0; j < 4; j++){
                int r = rb + j*32;
                cpa16(sbase + c*TILE_B + r*128 + swz16,
                      Cb + (size_t)r*2048 + c*128 + u16);
            }
            CP_COMMIT();
        }
        float acc[2][4][4]; ZERO_ACC4(acc);
        CP_WAIT(1);
        __syncthreads();
        compute64h64(sbase + 0*TILE_B, bBase0 + 0*TILE_S, RA, RB, TA, TB, acc);
        CP_WAIT(0);
        __syncthreads();
        compute64h64(sbase + 1*TILE_B, bBase0 + 1*TILE_S, RA, RB, TA, TB, acc);

        #pragma unroll
        for (int mi = 0; mi < 2; mi++){
            int r0 = warp_m + mi*16 + lg;
            #pragma unroll
            for (int ni = 0; ni < 4; ni++){
                int c2 = (warp_n + ni*8) / 2 + lk;
                stcg_u32(&P[r0*32 + c2],     pack_h2(acc[mi][ni][0], acc[mi][ni][1]));
                stcg_u32(&P[(r0+8)*32 + c2], pack_h2(acc[mi][ni][2], acc[mi][ni][3]));
            }
        }
        gsync(++bar, tid, cta);

        // phase B: sum 8 fp16 partials per y, GRU for 2 elements
        float2 y1 = make_float2(0.f, 0.f), y2 = make_float2(0.f, 0.f);
        int pidx = eb*32 + (hm >> 1);
        #pragma unroll
        for (int kk = 0; kk < 8; kk++){
            unsigned p1 = ldcg_u32(g_parth + (size_t)(nt1*8 + kk)*4096 + pidx);
            unsigned p2 = ldcg_u32(g_parth + (size_t)((nt1+16)*8 + kk)*4096 + pidx);
            float2 a = h2f2(p1); y1.x += a.x; y1.y += a.y;
            float2 b = h2f2(p2); y2.x += b.x; y2.y += b.y;
        }
        float2 fr0 = h2f2(fru), fw0 = h2f2(fwu);
        creg.x = gru_upd(fr0.x, fw0.x, y1.x, y2.x, vur.x, vu.x, creg.x, gg);
        creg.y = gru_upd(fr0.y, fw0.y, y1.y, y2.y, vur.y, vu.y, creg.y, gg);
        stcg_u32(&g_Ch[e >> 1], pack_h2(creg.x, creg.y));
        gsync(++bar, tid, cta);
    }
}

// ---------------- K5: final GEMM (pipelined split-K) ----------------
__global__ void __launch_bounds__(256,2) kD_out(){
    extern __shared__ unsigned us[];
    uint32_t sbase = smem_u32(us);
    int tid = threadIdx.x, wid = tid >> 5, lane = tid & 31;
    int lg = lane >> 2, lk = lane & 3;
    int warp_m = (wid >> 1) * 32, warp_n = (wid & 1) * 64;
    int nt = blockIdx.x, ks = blockIdx.y;
    int u16 = (tid & 7) * 16, rb = tid >> 3;
    uint32_t swz16 = (uint32_t)(((tid & 7) ^ (rb & 7)) * 16);
    LDSM_OFFSETS_H();
    int seg = ks >> 2;
    const unsigned* Asel = (seg == 0) ? g_pmh : (seg == 1 ? g_Ch : g_qh);
    const char* Ab = reinterpret_cast<const char*>(Asel) + (ks & 3) * 512;
    const char* Bb = reinterpret_cast<const char*>(g_Wmh) + (size_t)(nt*128)*6144 + ks*512;
    float acc[2][8][4]; ZERO_ACC(acc);

    const int NBLK = 4;
    GEMM_CPH(0, 0, Ab, 2048, Bb, 6144);
    GEMM_CPH(1, 1, Ab, 2048, Bb, 6144);
    int st = 0;
    for (int i = 0; i < NBLK; i++){
        CP_WAIT(1);
        __syncthreads();
        if (i + 2 < NBLK){
            int st2 = st + 2; if (st2 >= 3) st2 -= 3;
            GEMM_CPH(i+2, st2, Ab, 2048, Bb, 6144);
        }
        compute64h(sbase + st*TILE_B, sbase + (3+st)*TILE_B, RA, RB, TA, TB, acc);
        if (++st == 3) st = 0;
    }
    #pragma unroll
    for (int mi = 0; mi < 2; mi++){
        int r0 = warp_m + mi*16 + lg;
        #pragma unroll
        for (int ni = 0; ni < 8; ni++){
            int h = nt*128 + warp_n + ni*8 + lk*2;
            atomicAdd(&g_Otmp[(size_t)r0*HD + h     ], acc[mi][ni][0]);
            atomicAdd(&g_Otmp[(size_t)r0*HD + h + 1 ], acc[mi][ni][1]);
            atomicAdd(&g_Otmp[(size_t)(r0+8)*HD + h    ], acc[mi][ni][2]);
            atomicAdd(&g_Otmp[(size_t)(r0+8)*HD + h + 1], acc[mi][ni][3]);
        }
    }
}

// ---------------- K6: bias + relu ----------------
__global__ void k_finish(const float* __restrict__ bm, float* __restrict__ out){
    int i = blockIdx.x * blockDim.x + threadIdx.x;
    if (i < NB*HD){
        float v = g_Otmp[i] + bm[i & (HD-1)];
        out[i] = fmaxf(v, 0.f);
    }
}

// ---------------- launch ----------------
extern "C" void kernel_launch(void* const* d_in, const int* in_sizes, int n_in,
                              void* d_out, int out_size){
    (void)in_sizes; (void)n_in; (void)out_size;
    const float* facts     = (const float*)d_in[0];
    const float* questions = (const float*)d_in[1];
    const float* prevM     = (const float*)d_in[2];
    const float* Wr  = (const float*)d_in[3];
    const float* br  = (const float*)d_in[4];
    const float* Ur  = (const float*)d_in[5];
    const float* bur = (const float*)d_in[6];
    const float* W   = (const float*)d_in[7];
    const float* bw  = (const float*)d_in[8];
    const float* U   = (const float*)d_in[9];
    const float* bu  = (const float*)d_in[10];
    const float* Wz1 = (const float*)d_in[11];
    const float* bz1 = (const float*)d_in[12];
    const float* Wz2 = (const float*)d_in[13];
    const float* Wm  = (const float*)d_in[15];
    const float* bm  = (const float*)d_in[16];
    float* out = (float*)d_out;

    static int attr_done = 0;
    if (!attr_done){
        cudaFuncSetAttribute(kD_G,    cudaFuncAttributeMaxDynamicSharedMemorySize, GEMM_SMEM);
        cudaFuncSetAttribute(kD_F,    cudaFuncAttributeMaxDynamicSharedMemorySize, GEMM_SMEM);
        cudaFuncSetAttribute(kD_scan, cudaFuncAttributeMaxDynamicSharedMemorySize, SCAN_SMEM);
        cudaFuncSetAttribute(kD_out,  cudaFuncAttributeMaxDynamicSharedMemorySize, GEMM_SMEM);
        attr_done = 1;
    }

    unsigned *dWz1h, *dWrh, *dWh, *dUrh, *dUh, *dWmh, *dpmh, *dqh;
    cudaGetSymbolAddress((void**)&dWz1h, g_Wz1h);
    cudaGetSymbolAddress((void**)&dWrh,  g_Wrh);
    cudaGetSymbolAddress((void**)&dWh,   g_Wh);
    cudaGetSymbolAddress((void**)&dUrh,  g_Urh);
    cudaGetSymbolAddress((void**)&dUh,   g_Uh);
    cudaGetSymbolAddress((void**)&dWmh,  g_Wmh);
    cudaGetSymbolAddress((void**)&dpmh,  g_pmh);
    cudaGetSymbolAddress((void**)&dqh,   g_qh);

    k_init<<<512, 256>>>();
    k_zb_h<<<NROW, 256>>>(facts, questions, prevM);       // also emits g_fh
    k_cvt_h<<<1024, 256>>>((const float4*)Wz1, (uint2*)dWz1h, (HD*4*HD)/4);
    dim3 g4(512, 4);
    k_cvt4<<<g4, 256>>>((const float4*)Wr, (const float4*)W,
                        (const float4*)Ur, (const float4*)U,
                        (uint2*)dWrh, (uint2*)dWh, (uint2*)dUrh, (uint2*)dUh, (HD*HD)/4);
    k_cvt_h<<<1024, 256>>>((const float4*)Wm, (uint2*)dWmh, (HD*3*HD)/4);
    dim3 g2(128, 2);
    k_cvt4<<<g2, 256>>>((const float4*)prevM, (const float4*)questions,
                        (const float4*)prevM, (const float4*)questions,
                        (uint2*)dpmh, (uint2*)dqh, (uint2*)dpmh, (uint2*)dqh, (NB*HD)/4);
    dim3 gG(8, 128);
    kD_G<<<gG, 256, GEMM_SMEM>>>(bz1, Wz2);
    k_softmax<<<128, 128>>>();
    dim3 gF(8, 128, 2);
    kD_F<<<gF, 256, GEMM_SMEM>>>(br, bw);
    kD_scan<<<NCTA_SCAN, 256, SCAN_SMEM>>>(bur, bu);
    dim3 gO(8, 12);
    kD_out<<<gO, 256, GEMM_SMEM>>>();
    k_finish<<<512, 256>>>(bm, out);
}

// round 15
// speedup vs baseline: 1.0784x; 1.0784x over previous
#include <cuda_runtime.h>
#include <cuda_fp16.h>
#include <cstdint>
#include <cstddef>

#define HD 1024
#define NB 128
#define NS 128
#define NROW (NB*NS)
#define NCTA_SCAN 128
#define TILE_B 16384            // 128 rows x 64 fp16 (128B/row), swizzled
#define TILE_S 8192             // 64 rows x 64 fp16 (scan B)
#define GEMM_SMEM (6*TILE_B)    // 98304: 3xA + 3xB (2 CTAs/SM)
#define SCAN_SMEM (4*TILE_B + 4*TILE_S)  // 98304

// ---------------- scratch ----------------
__device__ __align__(16) unsigned g_FRh[(size_t)NS*NB*HD/2];
__device__ __align__(16) unsigned g_FWh[(size_t)NS*NB*HD/2];
__device__ __align__(16) unsigned g_Ch[NB*HD/2];
__device__ __align__(16) float g_Otmp[NB*HD];
__device__ __align__(16) unsigned g_parth[(size_t)NCTA_SCAN*4096];  // 128x64 fp16 per CTA
__device__ __align__(16) float g_Glogit[NROW];
__device__ __align__(16) float g_Gt[NS*NB];
__device__ __align__(16) unsigned g_fh[(size_t)NB*NS*HD/2];
__device__ __align__(16) unsigned g_zh[(size_t)NROW*4*HD/2];
__device__ __align__(16) unsigned g_Wz1h[(size_t)HD*4*HD/2];
__device__ __align__(16) unsigned g_Wrh[(size_t)HD*HD/2];
__device__ __align__(16) unsigned g_Wh[(size_t)HD*HD/2];
__device__ __align__(16) unsigned g_Urh[(size_t)HD*HD/2];
__device__ __align__(16) unsigned g_Uh[(size_t)HD*HD/2];
__device__ __align__(16) unsigned g_Wmh[(size_t)HD*3*HD/2];
__device__ __align__(16) unsigned g_pmh[NB*HD/2];
__device__ __align__(16) unsigned g_qh[NB*HD/2];
__device__ __align__(16) unsigned g_flags[NCTA_SCAN*32];

// ---------------- helpers ----------------
__device__ __forceinline__ unsigned pack_h2(float x, float y){
    __half2 h = __floats2half2_rn(x, y);
    return *reinterpret_cast<unsigned*>(&h);
}
__device__ __forceinline__ float2 h2f2(unsigned u){
    return __half22float2(*reinterpret_cast<const __half2*>(&u));
}
__device__ __forceinline__ uint32_t smem_u32(const void* p){
    uint32_t a; asm("{ .reg .u64 t; cvta.to.shared.u64 t, %1; cvt.u32.u64 %0, t; }"
                    : "=r"(a) : "l"(p)); return a;
}
__device__ __forceinline__ void cpa16(uint32_t dst, const void* src){
    asm volatile("cp.async.cg.shared.global [%0], [%1], 16;" :: "r"(dst), "l"(src));
}
#define CP_COMMIT() asm volatile("cp.async.commit_group;" ::: "memory")
#define CP_WAIT(n)  asm volatile("cp.async.wait_group %0;" :: "n"(n) : "memory")

__device__ __forceinline__ unsigned ldcg_u32(const unsigned* p){
    unsigned v; asm volatile("ld.global.cg.u32 %0, [%1];" : "=r"(v) : "l"(p)); return v;
}
__device__ __forceinline__ void stcg_u32(unsigned* p, unsigned v){
    asm volatile("st.global.cg.u32 [%0], %1;" :: "l"(p), "r"(v) : "memory");
}
__device__ __forceinline__ void ldsm4(unsigned* r, uint32_t addr){
    asm volatile("ldmatrix.sync.aligned.m8n8.x4.shared.b16 {%0,%1,%2,%3}, [%4];"
        : "=r"(r[0]),"=r"(r[1]),"=r"(r[2]),"=r"(r[3]) : "r"(addr));
}
__device__ __forceinline__ void mma16(float* d, const unsigned* a, const unsigned* b){
    asm volatile("mma.sync.aligned.m16n8k16.row.col.f32.f16.f16.f32 "
        "{%0,%1,%2,%3},{%4,%5,%6,%7},{%8,%9},{%0,%1,%2,%3};\n"
        : "+f"(d[0]),"+f"(d[1]),"+f"(d[2]),"+f"(d[3])
        : "r"(a[0]),"r"(a[1]),"r"(a[2]),"r"(a[3]),"r"(b[0]),"r"(b[1]));
}

__device__ __forceinline__ void compute64h(uint32_t aBase, uint32_t bBase,
        const uint32_t* RA, const uint32_t* RB, const uint32_t* TA, const uint32_t* TB,
        float acc[2][8][4]){
    #pragma unroll
    for (int ks = 0; ks < 4; ks++){
        unsigned a0[4], a1[4], bb[4][4];
        ldsm4(a0, aBase + RA[0] + TA[ks]);
        ldsm4(a1, aBase + RA[1] + TA[ks]);
        #pragma unroll
        for (int p = 0; p < 4; p++) ldsm4(bb[p], bBase + RB[p] + TB[ks]);
        #pragma unroll
        for (int mi = 0; mi < 2; mi++){
            const unsigned* a = mi ? a1 : a0;
            #pragma unroll
            for (int p = 0; p < 4; p++){
                unsigned bl[2] = {bb[p][0], bb[p][1]};
                unsigned bh[2] = {bb[p][2], bb[p][3]};
                mma16(acc[mi][2*p],   a, bl);
                mma16(acc[mi][2*p+1], a, bh);
            }
        }
    }
}

__device__ __forceinline__ void compute64h64(uint32_t aBase, uint32_t bBase,
        const uint32_t* RA, const uint32_t* RB, const uint32_t* TA, const uint32_t* TB,
        float acc[2][4][4]){
    #pragma unroll
    for (int ks = 0; ks < 4; ks++){
        unsigned a0[4], a1[4], bb[2][4];
        ldsm4(a0, aBase + RA[0] + TA[ks]);
        ldsm4(a1, aBase + RA[1] + TA[ks]);
        #pragma unroll
        for (int p = 0; p < 2; p++) ldsm4(bb[p], bBase + RB[p] + TB[ks]);
        #pragma unroll
        for (int mi = 0; mi < 2; mi++){
            const unsigned* a = mi ? a1 : a0;
            #pragma unroll
            for (int p = 0; p < 2; p++){
                unsigned bl[2] = {bb[p][0], bb[p][1]};
                unsigned bh[2] = {bb[p][2], bb[p][3]};
                mma16(acc[mi][2*p],   a, bl);
                mma16(acc[mi][2*p+1], a, bh);
            }
        }
    }
}

#define LDSM_OFFSETS_H() \
    int rowA = warp_m + (lane & 15); \
    uint32_t RA[2] = { (uint32_t)rowA*128u, (uint32_t)(rowA+16)*128u }; \
    uint32_t RB[4]; \
    _Pragma("unroll") for (int p_ = 0; p_ < 4; p_++) \
        RB[p_] = (uint32_t)(warp_n + p_*16 + (lane & 7) + ((lane >> 4) & 1)*8)*128u; \
    uint32_t TA[4], TB[4]; \
    _Pragma("unroll") for (int k_ = 0; k_ < 4; k_++){ \
        TA[k_] = (uint32_t)(((k_*2 + (lane >> 4)) ^ (rowA & 7))*16); \
        TB[k_] = (uint32_t)(((k_*2 + ((lane >> 3) & 1)) ^ (lane & 7))*16); }

#define LDSM_OFFSETS_H64() \
    int rowA = warp_m + (lane & 15); \
    uint32_t RA[2] = { (uint32_t)rowA*128u, (uint32_t)(rowA+16)*128u }; \
    uint32_t RB[2]; \
    _Pragma("unroll") for (int p_ = 0; p_ < 2; p_++) \
        RB[p_] = (uint32_t)(warp_n + p_*16 + (lane & 7) + ((lane >> 4) & 1)*8)*128u; \
    uint32_t TA[4], TB[4]; \
    _Pragma("unroll") for (int k_ = 0; k_ < 4; k_++){ \
        TA[k_] = (uint32_t)(((k_*2 + (lane >> 4)) ^ (rowA & 7))*16); \
        TB[k_] = (uint32_t)(((k_*2 + ((lane >> 3) & 1)) ^ (lane & 7))*16); }

#define ZERO_ACC(acc) { \
    _Pragma("unroll") for (int _i=0;_i<2;_i++) \
    _Pragma("unroll") for (int _j=0;_j<8;_j++) \
    _Pragma("unroll") for (int _k=0;_k<4;_k++) acc[_i][_j][_k]=0.f; }
#define ZERO_ACC4(acc) { \
    _Pragma("unroll") for (int _i=0;_i<2;_i++) \
    _Pragma("unroll") for (int _j=0;_j<4;_j++) \
    _Pragma("unroll") for (int _k=0;_k<4;_k++) acc[_i][_j][_k]=0.f; }

#define GEMM_CPH(i_, st_, Ab_, AldB_, Bb_, BldB_) { \
    size_t kb_ = (size_t)(i_)*128; \
    _Pragma("unroll") for (int j = 0; j < 4; j++){ int r_ = rb + j*32; \
        cpa16(sbase + (st_)*TILE_B + r_*128 + swz16, \
              (Ab_) + (size_t)r_*(AldB_) + kb_ + u16); \
        cpa16(sbase + (3 + (st_))*TILE_B + r_*128 + swz16, \
              (Bb_) + (size_t)r_*(BldB_) + kb_ + u16); } CP_COMMIT(); }

// ---------------- K0: per-replay init ----------------
__global__ void k_init(){
    int i = blockIdx.x * blockDim.x + threadIdx.x;
    if (i < NCTA_SCAN*32) g_flags[i] = 0u;
    if (i < NROW) g_Glogit[i] = 0.f;
    if (i < NB*HD/2) g_Ch[i] = 0u;
    if (i < NB*HD) g_Otmp[i] = 0.f;
}

// ---------------- Kc: fp32 -> fp16 bulk convert (batched) ----------------
__global__ void k_cvt_h(const float4* __restrict__ src, uint2* __restrict__ dst, int n4){
    for (int i = blockIdx.x*blockDim.x + threadIdx.x; i < n4; i += gridDim.x*blockDim.x){
        float4 v = src[i];
        dst[i] = make_uint2(pack_h2(v.x, v.y), pack_h2(v.z, v.w));
    }
}
__global__ void k_cvt4(const float4* __restrict__ s0, const float4* __restrict__ s1,
                       const float4* __restrict__ s2, const float4* __restrict__ s3,
                       uint2* d0, uint2* d1, uint2* d2, uint2* d3, int n4){
    int w = blockIdx.y;
    const float4* src = (w == 0) ? s0 : (w == 1) ? s1 : (w == 2) ? s2 : s3;
    uint2* dst = (w == 0) ? d0 : (w == 1) ? d1 : (w == 2) ? d2 : d3;
    for (int i = blockIdx.x*blockDim.x + threadIdx.x; i < n4; i += gridDim.x*blockDim.x){
        float4 v = src[i];
        dst[i] = make_uint2(pack_h2(v.x, v.y), pack_h2(v.z, v.w));
    }
}

// ---------------- Kz: build z (fp16) + facts fp16 ----------------
__global__ void k_zb_h(const float* __restrict__ facts, const float* __restrict__ q,
                       const float* __restrict__ pm){
    int row = blockIdx.x;
    int bt = row >> 7;
    int t = threadIdx.x;
    float4 f  = *reinterpret_cast<const float4*>(facts + (size_t)row*HD + t*4);
    float4 qv = *reinterpret_cast<const float4*>(q  + (size_t)bt*HD + t*4);
    float4 mv = *reinterpret_cast<const float4*>(pm + (size_t)bt*HD + t*4);
    char* zr = reinterpret_cast<char*>(g_zh) + (size_t)row*8192;
    *reinterpret_cast<uint2*>(reinterpret_cast<char*>(g_fh) + (size_t)row*2048 + t*8) =
        make_uint2(pack_h2(f.x, f.y), pack_h2(f.z, f.w));
    *reinterpret_cast<uint2*>(zr + 0*2048 + t*8) =
        make_uint2(pack_h2(f.x*qv.x, f.y*qv.y), pack_h2(f.z*qv.z, f.w*qv.w));
    *reinterpret_cast<uint2*>(zr + 1*2048 + t*8) =
        make_uint2(pack_h2(f.x*mv.x, f.y*mv.y), pack_h2(f.z*mv.z, f.w*mv.w));
    *reinterpret_cast<uint2*>(zr + 2*2048 + t*8) =
        make_uint2(pack_h2(fabsf(f.x-qv.x), fabsf(f.y-qv.y)), pack_h2(fabsf(f.z-qv.z), fabsf(f.w-qv.w)));
    *reinterpret_cast<uint2*>(zr + 3*2048 + t*8) =
        make_uint2(pack_h2(fabsf(f.x-mv.x), fabsf(f.y-mv.y)), pack_h2(fabsf(f.z-mv.z), fabsf(f.w-mv.w)));
}

// ================= K1: G logits =================
__global__ void __launch_bounds__(256,2) kE_G(
        const float* __restrict__ bz1, const float* __restrict__ Wz2){
    extern __shared__ unsigned us[];
    uint32_t sbase = smem_u32(us);
    int tid = threadIdx.x, wid = tid >> 5, lane = tid & 31;
    int lg = lane >> 2, lk = lane & 3;
    int warp_m = (wid >> 1) * 32, warp_n = (wid & 1) * 64;
    int nt = blockIdx.x, bt = blockIdx.y;
    int u16 = (tid & 7) * 16, rb = tid >> 3;
    uint32_t swz16 = (uint32_t)(((tid & 7) ^ (rb & 7)) * 16);
    LDSM_OFFSETS_H();
    const char* Ab = reinterpret_cast<const char*>(g_zh) + (size_t)bt*NS*8192;
    const char* Bb = reinterpret_cast<const char*>(g_Wz1h) + (size_t)(nt*128)*8192;
    float acc[2][8][4]; ZERO_ACC(acc);

    const int NBLK = 64;
    GEMM_CPH(0, 0, Ab, 8192, Bb, 8192);
    GEMM_CPH(1, 1, Ab, 8192, Bb, 8192);
    int st = 0;
    for (int i = 0; i < NBLK; i++){
        CP_WAIT(1);
        __syncthreads();
        if (i + 2 < NBLK){
            int st2 = st + 2; if (st2 >= 3) st2 -= 3;
            GEMM_CPH(i+2, st2, Ab, 8192, Bb, 8192);
        }
        compute64h(sbase + st*TILE_B, sbase + (3+st)*TILE_B, RA, RB, TA, TB, acc);
        if (++st == 3) st = 0;
    }

    float rs[4] = {0.f, 0.f, 0.f, 0.f};
    #pragma unroll
    for (int mi = 0; mi < 2; mi++)
        #pragma unroll
        for (int ni = 0; ni < 8; ni++){
            int c0 = nt*128 + warp_n + ni*8 + lk*2;
            float w0 = Wz2[c0], w1 = Wz2[c0+1];
            float z0 = bz1[c0], z1 = bz1[c0+1];
            rs[mi*2+0] += tanhf(acc[mi][ni][0]+z0)*w0 + tanhf(acc[mi][ni][1]+z1)*w1;
            rs[mi*2+1] += tanhf(acc[mi][ni][2]+z0)*w0 + tanhf(acc[mi][ni][3]+z1)*w1;
        }
    #pragma unroll
    for (int r = 0; r < 4; r++){
        rs[r] += __shfl_xor_sync(0xffffffffu, rs[r], 1);
        rs[r] += __shfl_xor_sync(0xffffffffu, rs[r], 2);
    }
    if (lk == 0){
        int s0 = warp_m + lg;
        atomicAdd(&g_Glogit[bt*NS + s0     ], rs[0]);
        atomicAdd(&g_Glogit[bt*NS + s0 + 8 ], rs[1]);
        atomicAdd(&g_Glogit[bt*NS + s0 + 16], rs[2]);
        atomicAdd(&g_Glogit[bt*NS + s0 + 24], rs[3]);
    }
}

// ================= K3: FR/FW (fp16 outputs) =================
__global__ void __launch_bounds__(256,2) kE_F(
        const float* __restrict__ br, const float* __restrict__ bw){
    extern __shared__ unsigned us[];
    uint32_t sbase = smem_u32(us);
    int tid = threadIdx.x, wid = tid >> 5, lane = tid & 31;
    int lg = lane >> 2, lk = lane & 3;
    int warp_m = (wid >> 1) * 32, warp_n = (wid & 1) * 64;
    int nt = blockIdx.x, bt = blockIdx.y, which = blockIdx.z;
    const unsigned* Wsel = which ? g_Wh : g_Wrh;
    const float*    bsel = which ? bw : br;
    unsigned* Outh = which ? g_FWh : g_FRh;
    int u16 = (tid & 7) * 16, rb = tid >> 3;
    uint32_t swz16 = (uint32_t)(((tid & 7) ^ (rb & 7)) * 16);
    LDSM_OFFSETS_H();
    const char* Ab = reinterpret_cast<const char*>(g_fh) + (size_t)bt*NS*2048;
    const char* Bb = reinterpret_cast<const char*>(Wsel) + (size_t)(nt*128)*2048;
    float acc[2][8][4]; ZERO_ACC(acc);

    const int NBLK = 16;
    GEMM_CPH(0, 0, Ab, 2048, Bb, 2048);
    GEMM_CPH(1, 1, Ab, 2048, Bb, 2048);
    int st = 0;
    for (int i = 0; i < NBLK; i++){
        CP_WAIT(1);
        __syncthreads();
        if (i + 2 < NBLK){
            int st2 = st + 2; if (st2 >= 3) st2 -= 3;
            GEMM_CPH(i+2, st2, Ab, 2048, Bb, 2048);
        }
        compute64h(sbase + st*TILE_B, sbase + (3+st)*TILE_B, RA, RB, TA, TB, acc);
        if (++st == 3) st = 0;
    }

    #pragma unroll
    for (int mi = 0; mi < 2; mi++){
        int r0 = warp_m + mi*16 + lg;
        #pragma unroll
        for (int ni = 0; ni < 8; ni++){
            int h = nt*128 + warp_n + ni*8 + lk*2;
            float b0 = bsel[h], b1 = bsel[h+1];
            Outh[((size_t)r0*(NB*HD) + (size_t)bt*HD + h) >> 1] =
                pack_h2(acc[mi][ni][0]+b0, acc[mi][ni][1]+b1);
            Outh[((size_t)(r0+8)*(NB*HD) + (size_t)bt*HD + h) >> 1] =
                pack_h2(acc[mi][ni][2]+b0, acc[mi][ni][3]+b1);
        }
    }
}

// ---------------- K2: softmax ----------------
__global__ void k_softmax(){
    int bt = blockIdx.x, t = threadIdx.x;
    float v = g_Glogit[bt*NS + t];
    __shared__ float sm_[4], ss[4];
    float mx = v;
    #pragma unroll
    for (int o = 16; o; o >>= 1) mx = fmaxf(mx, __shfl_xor_sync(0xffffffffu, mx, o));
    if ((t & 31) == 0) sm_[t >> 5] = mx;
    __syncthreads();
    mx = fmaxf(fmaxf(sm_[0], sm_[1]), fmaxf(sm_[2], sm_[3]));
    float e = __expf(v - mx);
    float sum = e;
    #pragma unroll
    for (int o = 16; o; o >>= 1) sum += __shfl_xor_sync(0xffffffffu, sum, o);
    if ((t & 31) == 0) ss[t >> 5] = sum;
    __syncthreads();
    sum = ss[0] + ss[1] + ss[2] + ss[3];
    g_Gt[t*NB + bt] = e / sum;
}

// ---------------- K4: persistent scan (R11 config: 128 CTAs, 32 nt x 4 K) ----------------
__device__ __forceinline__ void gsync(unsigned step, int tid, int cta){
    __syncthreads();
    if (tid == 0){
        __threadfence();
        stcg_u32(&g_flags[cta*32], step);
    }
    if (tid < NCTA_SCAN){
        while (ldcg_u32(&g_flags[tid*32]) < step) { }
    }
    __threadfence();
    __syncthreads();
}
__device__ __forceinline__ float gru_upd(float fr, float fw, float y1, float y2,
                                         float b_ur, float b_u, float c, float g){
    float r  = 1.f / (1.f + __expf(-(fr + y1 + b_ur)));
    float ht = tanhf(fw + r * (y2 + b_u));
    return g * ht + (1.f - g) * c;
}

__global__ void __launch_bounds__(256,1) kE_scan(
        const float* __restrict__ bur, const float* __restrict__ bu){
    extern __shared__ unsigned us[];   // A subs: 4 x TILE_B; B resident: 4 x TILE_S at 4*TILE_B
    uint32_t sbase = smem_u32(us);
    int cta = blockIdx.x, tid = threadIdx.x;
    int wid = tid >> 5, lane = tid & 31, lg = lane >> 2, lk = lane & 3;
    int warp_m = (wid & 3) * 32, warp_n = (wid >> 2) * 32;
    int u16 = (tid & 7) * 16, rb = tid >> 3;
    uint32_t swz16 = (uint32_t)(((tid & 7) ^ (rb & 7)) * 16);
    LDSM_OFFSETS_H64();
    int nt  = cta >> 2;             // 0..31: 0-15 Y1 (Ur), 16-31 Y2 (U)
    int knt = cta & 3;              // K slice
    int kcb = knt * 256;            // K base (halves)
    const unsigned* Wsel = (nt < 16) ? g_Urh : g_Uh;
    int nbase = (nt & 15) * 64;
    unsigned* P = g_parth + (size_t)cta * 4096;   // 128x64 halves
    const char* Wb = reinterpret_cast<const char*>(Wsel) + (size_t)nbase*2048 + kcb*2;
    const char* Cb = reinterpret_cast<const char*>(g_Ch) + kcb*2;
    uint32_t bBase0 = sbase + 4*TILE_B;

    // resident fp16 weights: 4 chunks of 64 rows x 64 K
    #pragma unroll
    for (int j = 0; j < 8; j++){
        int c = j >> 1, n = rb + (j & 1)*32;
        cpa16(bBase0 + c*TILE_S + n*128 + swz16,
              Wb + (size_t)n*2048 + c*128 + u16);
    }
    CP_COMMIT();
    CP_WAIT(0);
    __syncthreads();

    int e  = (cta*256 + tid) * 4;   // 4 consecutive h per thread
    int eb = e >> 10, eh = e & (HD-1);
    int nt1 = eh >> 6, hm = eh & 63;
    float4 vur = *reinterpret_cast<const float4*>(bur + eh);
    float4 vu  = *reinterpret_cast<const float4*>(bu + eh);
    float4 creg = make_float4(0.f, 0.f, 0.f, 0.f);

    unsigned bar = 0;
    for (int s = 0; s < NS; s++){
        size_t fi = (((size_t)s*NB + eb)*HD + eh) >> 1;
        uint2 fru = *reinterpret_cast<const uint2*>(g_FRh + fi);
        uint2 fwu = *reinterpret_cast<const uint2*>(g_FWh + fi);
        float gg = g_Gt[s*NB + eb];

        // phase A: C slice (fp16), 4 sub-tiles of 64K, resident weights
        #pragma unroll
        for (int sg = 0; sg < 4; sg++){
            #pragma unroll
            for (int j = 0; j < 4; j++){
                int r = rb + j*32;
                cpa16(sbase + sg*TILE_B + r*128 + swz16,
                      Cb + (size_t)r*2048 + sg*128 + u16);
            }
            CP_COMMIT();
        }
        float acc[2][4][4]; ZERO_ACC4(acc);
        #pragma unroll
        for (int sub = 0; sub < 4; sub++){
            if (sub == 0)      CP_WAIT(3);
            else if (sub == 1) CP_WAIT(2);
            else if (sub == 2) CP_WAIT(1);
            else               CP_WAIT(0);
            __syncthreads();
            compute64h64(sbase + sub*TILE_B, bBase0 + sub*TILE_S, RA, RB, TA, TB, acc);
        }
        #pragma unroll
        for (int mi = 0; mi < 2; mi++){
            int r0 = warp_m + mi*16 + lg;
            #pragma unroll
            for (int ni = 0; ni < 4; ni++){
                int c2 = (warp_n + ni*8) / 2 + lk;
                stcg_u32(&P[r0*32 + c2],     pack_h2(acc[mi][ni][0], acc[mi][ni][1]));
                stcg_u32(&P[(r0+8)*32 + c2], pack_h2(acc[mi][ni][2], acc[mi][ni][3]));
            }
        }
        gsync(++bar, tid, cta);

        // phase B: reduce 4 fp16 partials per y, GRU update
        float2 y1a = make_float2(0,0), y1b = make_float2(0,0);
        float2 y2a = make_float2(0,0), y2b = make_float2(0,0);
        int pidx = eb*32 + (hm >> 1);
        #pragma unroll
        for (int kk = 0; kk < 4; kk++){
            uint2 p1 = *reinterpret_cast<const uint2*>(
                g_parth + (size_t)(nt1*4 + kk)*4096 + pidx);
            uint2 p2 = *reinterpret_cast<const uint2*>(
                g_parth + (size_t)((nt1+16)*4 + kk)*4096 + pidx);
            float2 a = h2f2(p1.x), b = h2f2(p1.y);
            y1a.x += a.x; y1a.y += a.y; y1b.x += b.x; y1b.y += b.y;
            float2 c = h2f2(p2.x), d = h2f2(p2.y);
            y2a.x += c.x; y2a.y += c.y; y2b.x += d.x; y2b.y += d.y;
        }
        float2 fr0 = h2f2(fru.x), fr1 = h2f2(fru.y);
        float2 fw0 = h2f2(fwu.x), fw1 = h2f2(fwu.y);
        creg.x = gru_upd(fr0.x, fw0.x, y1a.x, y2a.x, vur.x, vu.x, creg.x, gg);
        creg.y = gru_upd(fr0.y, fw0.y, y1a.y, y2a.y, vur.y, vu.y, creg.y, gg);
        creg.z = gru_upd(fr1.x, fw1.x, y1b.x, y2b.x, vur.z, vu.z, creg.z, gg);
        creg.w = gru_upd(fr1.y, fw1.y, y1b.y, y2b.y, vur.w, vu.w, creg.w, gg);
        __stcg(reinterpret_cast<uint2*>(g_Ch + (e >> 1)),
               make_uint2(pack_h2(creg.x, creg.y), pack_h2(creg.z, creg.w)));
        gsync(++bar, tid, cta);
    }
}

// ---------------- K5: final GEMM (pipelined split-K) ----------------
__global__ void __launch_bounds__(256,2) kE_out(){
    extern __shared__ unsigned us[];
    uint32_t sbase = smem_u32(us);
    int tid = threadIdx.x, wid = tid >> 5, lane = tid & 31;
    int lg = lane >> 2, lk = lane & 3;
    int warp_m = (wid >> 1) * 32, warp_n = (wid & 1) * 64;
    int nt = blockIdx.x, ks = blockIdx.y;
    int u16 = (tid & 7) * 16, rb = tid >> 3;
    uint32_t swz16 = (uint32_t)(((tid & 7) ^ (rb & 7)) * 16);
    LDSM_OFFSETS_H();
    int seg = ks >> 2;
    const unsigned* Asel = (seg == 0) ? g_pmh : (seg == 1 ? g_Ch : g_qh);
    const char* Ab = reinterpret_cast<const char*>(Asel) + (ks & 3) * 512;
    const char* Bb = reinterpret_cast<const char*>(g_Wmh) + (size_t)(nt*128)*6144 + ks*512;
    float acc[2][8][4]; ZERO_ACC(acc);

    const int NBLK = 4;
    GEMM_CPH(0, 0, Ab, 2048, Bb, 6144);
    GEMM_CPH(1, 1, Ab, 2048, Bb, 6144);
    int st = 0;
    for (int i = 0; i < NBLK; i++){
        CP_WAIT(1);
        __syncthreads();
        if (i + 2 < NBLK){
            int st2 = st + 2; if (st2 >= 3) st2 -= 3;
            GEMM_CPH(i+2, st2, Ab, 2048, Bb, 6144);
        }
        compute64h(sbase + st*TILE_B, sbase + (3+st)*TILE_B, RA, RB, TA, TB, acc);
        if (++st == 3) st = 0;
    }
    #pragma unroll
    for (int mi = 0; mi < 2; mi++){
        int r0 = warp_m + mi*16 + lg;
        #pragma unroll
        for (int ni = 0; ni < 8; ni++){
            int h = nt*128 + warp_n + ni*8 + lk*2;
            atomicAdd(&g_Otmp[(size_t)r0*HD + h     ], acc[mi][ni][0]);
            atomicAdd(&g_Otmp[(size_t)r0*HD + h + 1 ], acc[mi][ni][1]);
            atomicAdd(&g_Otmp[(size_t)(r0+8)*HD + h    ], acc[mi][ni][2]);
            atomicAdd(&g_Otmp[(size_t)(r0+8)*HD + h + 1], acc[mi][ni][3]);
        }
    }
}

// ---------------- K6: bias + relu ----------------
__global__ void k_finish(const float* __restrict__ bm, float* __restrict__ out){
    int i = blockIdx.x * blockDim.x + threadIdx.x;
    if (i < NB*HD){
        float v = g_Otmp[i] + bm[i & (HD-1)];
        out[i] = fmaxf(v, 0.f);
    }
}

// ---------------- launch ----------------
extern "C" void kernel_launch(void* const* d_in, const int* in_sizes, int n_in,
                              void* d_out, int out_size){
    (void)in_sizes; (void)n_in; (void)out_size;
    const float* facts     = (const float*)d_in[0];
    const float* questions = (const float*)d_in[1];
    const float* prevM     = (const float*)d_in[2];
    const float* Wr  = (const float*)d_in[3];
    const float* br  = (const float*)d_in[4];
    const float* Ur  = (const float*)d_in[5];
    const float* bur = (const float*)d_in[6];
    const float* W   = (const float*)d_in[7];
    const float* bw  = (const float*)d_in[8];
    const float* U   = (const float*)d_in[9];
    const float* bu  = (const float*)d_in[10];
    const float* Wz1 = (const float*)d_in[11];
    const float* bz1 = (const float*)d_in[12];
    const float* Wz2 = (const float*)d_in[13];
    const float* Wm  = (const float*)d_in[15];
    const float* bm  = (const float*)d_in[16];
    float* out = (float*)d_out;

    static int attr_done = 0;
    if (!attr_done){
        cudaFuncSetAttribute(kE_G,    cudaFuncAttributeMaxDynamicSharedMemorySize, GEMM_SMEM);
        cudaFuncSetAttribute(kE_F,    cudaFuncAttributeMaxDynamicSharedMemorySize, GEMM_SMEM);
        cudaFuncSetAttribute(kE_scan, cudaFuncAttributeMaxDynamicSharedMemorySize, SCAN_SMEM);
        cudaFuncSetAttribute(kE_out,  cudaFuncAttributeMaxDynamicSharedMemorySize, GEMM_SMEM);
        attr_done = 1;
    }

    unsigned *dWz1h, *dWrh, *dWh, *dUrh, *dUh, *dWmh, *dpmh, *dqh;
    cudaGetSymbolAddress((void**)&dWz1h, g_Wz1h);
    cudaGetSymbolAddress((void**)&dWrh,  g_Wrh);
    cudaGetSymbolAddress((void**)&dWh,   g_Wh);
    cudaGetSymbolAddress((void**)&dUrh,  g_Urh);
    cudaGetSymbolAddress((void**)&dUh,   g_Uh);
    cudaGetSymbolAddress((void**)&dWmh,  g_Wmh);
    cudaGetSymbolAddress((void**)&dpmh,  g_pmh);
    cudaGetSymbolAddress((void**)&dqh,   g_qh);

    k_init<<<512, 256>>>();
    k_zb_h<<<NROW, 256>>>(facts, questions, prevM);       // also emits g_fh
    k_cvt_h<<<1024, 256>>>((const float4*)Wz1, (uint2*)dWz1h, (HD*4*HD)/4);
    dim3 g4(512, 4);
    k_cvt4<<<g4, 256>>>((const float4*)Wr, (const float4*)W,
                        (const float4*)Ur, (const float4*)U,
                        (uint2*)dWrh, (uint2*)dWh, (uint2*)dUrh, (uint2*)dUh, (HD*HD)/4);
    k_cvt_h<<<1024, 256>>>((const float4*)Wm, (uint2*)dWmh, (HD*3*HD)/4);
    dim3 g2(128, 2);
    k_cvt4<<<g2, 256>>>((const float4*)prevM, (const float4*)questions,
                        (const float4*)prevM, (const float4*)questions,
                        (uint2*)dpmh, (uint2*)dqh, (uint2*)dpmh, (uint2*)dqh, (NB*HD)/4);
    dim3 gG(8, 128);
    kE_G<<<gG, 256, GEMM_SMEM>>>(bz1, Wz2);
    k_softmax<<<128, 128>>>();
    dim3 gF(8, 128, 2);
    kE_F<<<gF, 256, GEMM_SMEM>>>(br, bw);
    kE_scan<<<NCTA_SCAN, 256, SCAN_SMEM>>>(bur, bu);
    dim3 gO(8, 12);
    kE_out<<<gO, 256, GEMM_SMEM>>>();
    k_finish<<<512, 256>>>(bm, out);
}

// round 17
// speedup vs baseline: 1.0922x; 1.0127x over previous
#include <cuda_runtime.h>
#include <cuda_fp16.h>
#include <cstdint>
#include <cstddef>

#define HD 1024
#define NB 128
#define NS 128
#define NROW (NB*NS)
#define NCTA_SCAN 128
#define TILE_B 16384            // 128 rows x 64 fp16 (128B/row), swizzled
#define TILE_S 8192             // 64 rows x 64 fp16 (scan B)
#define GEMM_SMEM (6*TILE_B)    // 98304: 3xA + 3xB (2 CTAs/SM)
#define SCAN_SMEM (4*TILE_B + 4*TILE_S)  // 98304

// ---------------- scratch ----------------
__device__ __align__(16) unsigned g_FRh[(size_t)NS*NB*HD/2];
__device__ __align__(16) unsigned g_FWh[(size_t)NS*NB*HD/2];
__device__ __align__(16) unsigned g_Ch[NB*HD/2];
__device__ __align__(16) float g_Otmp[NB*HD];
__device__ __align__(16) unsigned g_parth[(size_t)NCTA_SCAN*4096];  // 128x64 fp16 per CTA
__device__ __align__(16) float g_Glogit[NROW];
__device__ __align__(16) float g_Gt[NS*NB];
__device__ __align__(16) unsigned g_fh[(size_t)NB*NS*HD/2];
__device__ __align__(16) unsigned g_zh[(size_t)NROW*4*HD/2];
__device__ __align__(16) unsigned g_Wz1h[(size_t)HD*4*HD/2];
__device__ __align__(16) unsigned g_Wrh[(size_t)HD*HD/2];
__device__ __align__(16) unsigned g_Wh[(size_t)HD*HD/2];
__device__ __align__(16) unsigned g_Urh[(size_t)HD*HD/2];
__device__ __align__(16) unsigned g_Uh[(size_t)HD*HD/2];
__device__ __align__(16) unsigned g_Wmh[(size_t)HD*3*HD/2];
__device__ __align__(16) unsigned g_pmh[NB*HD/2];
__device__ __align__(16) unsigned g_qh[NB*HD/2];
__device__ __align__(16) unsigned g_flags[NCTA_SCAN*32];

// ---------------- helpers ----------------
__device__ __forceinline__ unsigned pack_h2(float x, float y){
    __half2 h = __floats2half2_rn(x, y);
    return *reinterpret_cast<unsigned*>(&h);
}
__device__ __forceinline__ float2 h2f2(unsigned u){
    return __half22float2(*reinterpret_cast<const __half2*>(&u));
}
__device__ __forceinline__ uint32_t smem_u32(const void* p){
    uint32_t a; asm("{ .reg .u64 t; cvta.to.shared.u64 t, %1; cvt.u32.u64 %0, t; }"
                    : "=r"(a) : "l"(p)); return a;
}
__device__ __forceinline__ void cpa16(uint32_t dst, const void* src){
    asm volatile("cp.async.cg.shared.global [%0], [%1], 16;" :: "r"(dst), "l"(src));
}
#define CP_COMMIT() asm volatile("cp.async.commit_group;" ::: "memory")
#define CP_WAIT(n)  asm volatile("cp.async.wait_group %0;" :: "n"(n) : "memory")

__device__ __forceinline__ unsigned ldcg_u32(const unsigned* p){
    unsigned v; asm volatile("ld.global.cg.u32 %0, [%1];" : "=r"(v) : "l"(p)); return v;
}
__device__ __forceinline__ void stcg_u32(unsigned* p, unsigned v){
    asm volatile("st.global.cg.u32 [%0], %1;" :: "l"(p), "r"(v) : "memory");
}
__device__ __forceinline__ void st_release(unsigned* p, unsigned v){
    asm volatile("st.release.gpu.u32 [%0], %1;" :: "l"(p), "r"(v) : "memory");
}
__device__ __forceinline__ void ldsm4(unsigned* r, uint32_t addr){
    asm volatile("ldmatrix.sync.aligned.m8n8.x4.shared.b16 {%0,%1,%2,%3}, [%4];"
        : "=r"(r[0]),"=r"(r[1]),"=r"(r[2]),"=r"(r[3]) : "r"(addr));
}
__device__ __forceinline__ void mma16(float* d, const unsigned* a, const unsigned* b){
    asm volatile("mma.sync.aligned.m16n8k16.row.col.f32.f16.f16.f32 "
        "{%0,%1,%2,%3},{%4,%5,%6,%7},{%8,%9},{%0,%1,%2,%3};\n"
        : "+f"(d[0]),"+f"(d[1]),"+f"(d[2]),"+f"(d[3])
        : "r"(a[0]),"r"(a[1]),"r"(a[2]),"r"(a[3]),"r"(b[0]),"r"(b[1]));
}

__device__ __forceinline__ void compute64h(uint32_t aBase, uint32_t bBase,
        const uint32_t* RA, const uint32_t* RB, const uint32_t* TA, const uint32_t* TB,
        float acc[2][8][4]){
    #pragma unroll
    for (int ks = 0; ks < 4; ks++){
        unsigned a0[4], a1[4], bb[4][4];
        ldsm4(a0, aBase + RA[0] + TA[ks]);
        ldsm4(a1, aBase + RA[1] + TA[ks]);
        #pragma unroll
        for (int p = 0; p < 4; p++) ldsm4(bb[p], bBase + RB[p] + TB[ks]);
        #pragma unroll
        for (int mi = 0; mi < 2; mi++){
            const unsigned* a = mi ? a1 : a0;
            #pragma unroll
            for (int p = 0; p < 4; p++){
                unsigned bl[2] = {bb[p][0], bb[p][1]};
                unsigned bh[2] = {bb[p][2], bb[p][3]};
                mma16(acc[mi][2*p],   a, bl);
                mma16(acc[mi][2*p+1], a, bh);
            }
        }
    }
}

__device__ __forceinline__ void compute64h64(uint32_t aBase, uint32_t bBase,
        const uint32_t* RA, const uint32_t* RB, const uint32_t* TA, const uint32_t* TB,
        float acc[2][4][4]){
    #pragma unroll
    for (int ks = 0; ks < 4; ks++){
        unsigned a0[4], a1[4], bb[2][4];
        ldsm4(a0, aBase + RA[0] + TA[ks]);
        ldsm4(a1, aBase + RA[1] + TA[ks]);
        #pragma unroll
        for (int p = 0; p < 2; p++) ldsm4(bb[p], bBase + RB[p] + TB[ks]);
        #pragma unroll
        for (int mi = 0; mi < 2; mi++){
            const unsigned* a = mi ? a1 : a0;
            #pragma unroll
            for (int p = 0; p < 2; p++){
                unsigned bl[2] = {bb[p][0], bb[p][1]};
                unsigned bh[2] = {bb[p][2], bb[p][3]};
                mma16(acc[mi][2*p],   a, bl);
                mma16(acc[mi][2*p+1], a, bh);
            }
        }
    }
}

#define LDSM_OFFSETS_H() \
    int rowA = warp_m + (lane & 15); \
    uint32_t RA[2] = { (uint32_t)rowA*128u, (uint32_t)(rowA+16)*128u }; \
    uint32_t RB[4]; \
    _Pragma("unroll") for (int p_ = 0; p_ < 4; p_++) \
        RB[p_] = (uint32_t)(warp_n + p_*16 + (lane & 7) + ((lane >> 4) & 1)*8)*128u; \
    uint32_t TA[4], TB[4]; \
    _Pragma("unroll") for (int k_ = 0; k_ < 4; k_++){ \
        TA[k_] = (uint32_t)(((k_*2 + (lane >> 4)) ^ (rowA & 7))*16); \
        TB[k_] = (uint32_t)(((k_*2 + ((lane >> 3) & 1)) ^ (lane & 7))*16); }

#define LDSM_OFFSETS_H64() \
    int rowA = warp_m + (lane & 15); \
    uint32_t RA[2] = { (uint32_t)rowA*128u, (uint32_t)(rowA+16)*128u }; \
    uint32_t RB[2]; \
    _Pragma("unroll") for (int p_ = 0; p_ < 2; p_++) \
        RB[p_] = (uint32_t)(warp_n + p_*16 + (lane & 7) + ((lane >> 4) & 1)*8)*128u; \
    uint32_t TA[4], TB[4]; \
    _Pragma("unroll") for (int k_ = 0; k_ < 4; k_++){ \
        TA[k_] = (uint32_t)(((k_*2 + (lane >> 4)) ^ (rowA & 7))*16); \
        TB[k_] = (uint32_t)(((k_*2 + ((lane >> 3) & 1)) ^ (lane & 7))*16); }

#define ZERO_ACC(acc) { \
    _Pragma("unroll") for (int _i=0;_i<2;_i++) \
    _Pragma("unroll") for (int _j=0;_j<8;_j++) \
    _Pragma("unroll") for (int _k=0;_k<4;_k++) acc[_i][_j][_k]=0.f; }
#define ZERO_ACC4(acc) { \
    _Pragma("unroll") for (int _i=0;_i<2;_i++) \
    _Pragma("unroll") for (int _j=0;_j<4;_j++) \
    _Pragma("unroll") for (int _k=0;_k<4;_k++) acc[_i][_j][_k]=0.f; }

#define GEMM_CPH(i_, st_, Ab_, AldB_, Bb_, BldB_) { \
    size_t kb_ = (size_t)(i_)*128; \
    _Pragma("unroll") for (int j = 0; j < 4; j++){ int r_ = rb + j*32; \
        cpa16(sbase + (st_)*TILE_B + r_*128 + swz16, \
              (Ab_) + (size_t)r_*(AldB_) + kb_ + u16); \
        cpa16(sbase + (3 + (st_))*TILE_B + r_*128 + swz16, \
              (Bb_) + (size_t)r_*(BldB_) + kb_ + u16); } CP_COMMIT(); }

// ---------------- K0: per-replay init ----------------
__global__ void k_init(){
    int i = blockIdx.x * blockDim.x + threadIdx.x;
    if (i < NCTA_SCAN*32) g_flags[i] = 0u;
    if (i < NROW) g_Glogit[i] = 0.f;
    if (i < NB*HD/2) g_Ch[i] = 0u;
    if (i < NB*HD) g_Otmp[i] = 0.f;
}

// ---------------- Kc: fp32 -> fp16 bulk convert (batched) ----------------
__global__ void k_cvt_h(const float4* __restrict__ src, uint2* __restrict__ dst, int n4){
    for (int i = blockIdx.x*blockDim.x + threadIdx.x; i < n4; i += gridDim.x*blockDim.x){
        float4 v = src[i];
        dst[i] = make_uint2(pack_h2(v.x, v.y), pack_h2(v.z, v.w));
    }
}
__global__ void k_cvt4(const float4* __restrict__ s0, const float4* __restrict__ s1,
                       const float4* __restrict__ s2, const float4* __restrict__ s3,
                       uint2* d0, uint2* d1, uint2* d2, uint2* d3, int n4){
    int w = blockIdx.y;
    const float4* src = (w == 0) ? s0 : (w == 1) ? s1 : (w == 2) ? s2 : s3;
    uint2* dst = (w == 0) ? d0 : (w == 1) ? d1 : (w == 2) ? d2 : d3;
    for (int i = blockIdx.x*blockDim.x + threadIdx.x; i < n4; i += gridDim.x*blockDim.x){
        float4 v = src[i];
        dst[i] = make_uint2(pack_h2(v.x, v.y), pack_h2(v.z, v.w));
    }
}

// ---------------- Kz: build z (fp16) + facts fp16 ----------------
__global__ void k_zb_h(const float* __restrict__ facts, const float* __restrict__ q,
                       const float* __restrict__ pm){
    int row = blockIdx.x;
    int bt = row >> 7;
    int t = threadIdx.x;
    float4 f  = *reinterpret_cast<const float4*>(facts + (size_t)row*HD + t*4);
    float4 qv = *reinterpret_cast<const float4*>(q  + (size_t)bt*HD + t*4);
    float4 mv = *reinterpret_cast<const float4*>(pm + (size_t)bt*HD + t*4);
    char* zr = reinterpret_cast<char*>(g_zh) + (size_t)row*8192;
    *reinterpret_cast<uint2*>(reinterpret_cast<char*>(g_fh) + (size_t)row*2048 + t*8) =
        make_uint2(pack_h2(f.x, f.y), pack_h2(f.z, f.w));
    *reinterpret_cast<uint2*>(zr + 0*2048 + t*8) =
        make_uint2(pack_h2(f.x*qv.x, f.y*qv.y), pack_h2(f.z*qv.z, f.w*qv.w));
    *reinterpret_cast<uint2*>(zr + 1*2048 + t*8) =
        make_uint2(pack_h2(f.x*mv.x, f.y*mv.y), pack_h2(f.z*mv.z, f.w*mv.w));
    *reinterpret_cast<uint2*>(zr + 2*2048 + t*8) =
        make_uint2(pack_h2(fabsf(f.x-qv.x), fabsf(f.y-qv.y)), pack_h2(fabsf(f.z-qv.z), fabsf(f.w-qv.w)));
    *reinterpret_cast<uint2*>(zr + 3*2048 + t*8) =
        make_uint2(pack_h2(fabsf(f.x-mv.x), fabsf(f.y-mv.y)), pack_h2(fabsf(f.z-mv.z), fabsf(f.w-mv.w)));
}

// ================= K1: G logits =================
__global__ void __launch_bounds__(256,2) kF_G(
        const float* __restrict__ bz1, const float* __restrict__ Wz2){
    extern __shared__ unsigned us[];
    uint32_t sbase = smem_u32(us);
    int tid = threadIdx.x, wid = tid >> 5, lane = tid & 31;
    int lg = lane >> 2, lk = lane & 3;
    int warp_m = (wid >> 1) * 32, warp_n = (wid & 1) * 64;
    int nt = blockIdx.x, bt = blockIdx.y;
    int u16 = (tid & 7) * 16, rb = tid >> 3;
    uint32_t swz16 = (uint32_t)(((tid & 7) ^ (rb & 7)) * 16);
    LDSM_OFFSETS_H();
    const char* Ab = reinterpret_cast<const char*>(g_zh) + (size_t)bt*NS*8192;
    const char* Bb = reinterpret_cast<const char*>(g_Wz1h) + (size_t)(nt*128)*8192;
    float acc[2][8][4]; ZERO_ACC(acc);

    const int NBLK = 64;
    GEMM_CPH(0, 0, Ab, 8192, Bb, 8192);
    GEMM_CPH(1, 1, Ab, 8192, Bb, 8192);
    int st = 0;
    for (int i = 0; i < NBLK; i++){
        CP_WAIT(1);
        __syncthreads();
        if (i + 2 < NBLK){
            int st2 = st + 2; if (st2 >= 3) st2 -= 3;
            GEMM_CPH(i+2, st2, Ab, 8192, Bb, 8192);
        }
        compute64h(sbase + st*TILE_B, sbase + (3+st)*TILE_B, RA, RB, TA, TB, acc);
        if (++st == 3) st = 0;
    }

    float rs[4] = {0.f, 0.f, 0.f, 0.f};
    #pragma unroll
    for (int mi = 0; mi < 2; mi++)
        #pragma unroll
        for (int ni = 0; ni < 8; ni++){
            int c0 = nt*128 + warp_n + ni*8 + lk*2;
            float w0 = Wz2[c0], w1 = Wz2[c0+1];
            float z0 = bz1[c0], z1 = bz1[c0+1];
            rs[mi*2+0] += tanhf(acc[mi][ni][0]+z0)*w0 + tanhf(acc[mi][ni][1]+z1)*w1;
            rs[mi*2+1] += tanhf(acc[mi][ni][2]+z0)*w0 + tanhf(acc[mi][ni][3]+z1)*w1;
        }
    #pragma unroll
    for (int r = 0; r < 4; r++){
        rs[r] += __shfl_xor_sync(0xffffffffu, rs[r], 1);
        rs[r] += __shfl_xor_sync(0xffffffffu, rs[r], 2);
    }
    if (lk == 0){
        int s0 = warp_m + lg;
        atomicAdd(&g_Glogit[bt*NS + s0     ], rs[0]);
        atomicAdd(&g_Glogit[bt*NS + s0 + 8 ], rs[1]);
        atomicAdd(&g_Glogit[bt*NS + s0 + 16], rs[2]);
        atomicAdd(&g_Glogit[bt*NS + s0 + 24], rs[3]);
    }
}

// ================= K3: FR/FW (fp16 outputs) =================
__global__ void __launch_bounds__(256,2) kF_F(
        const float* __restrict__ br, const float* __restrict__ bw){
    extern __shared__ unsigned us[];
    uint32_t sbase = smem_u32(us);
    int tid = threadIdx.x, wid = tid >> 5, lane = tid & 31;
    int lg = lane >> 2, lk = lane & 3;
    int warp_m = (wid >> 1) * 32, warp_n = (wid & 1) * 64;
    int nt = blockIdx.x, bt = blockIdx.y, which = blockIdx.z;
    const unsigned* Wsel = which ? g_Wh : g_Wrh;
    const float*    bsel = which ? bw : br;
    unsigned* Outh = which ? g_FWh : g_FRh;
    int u16 = (tid & 7) * 16, rb = tid >> 3;
    uint32_t swz16 = (uint32_t)(((tid & 7) ^ (rb & 7)) * 16);
    LDSM_OFFSETS_H();
    const char* Ab = reinterpret_cast<const char*>(g_fh) + (size_t)bt*NS*2048;
    const char* Bb = reinterpret_cast<const char*>(Wsel) + (size_t)(nt*128)*2048;
    float acc[2][8][4]; ZERO_ACC(acc);

    const int NBLK = 16;
    GEMM_CPH(0, 0, Ab, 2048, Bb, 2048);
    GEMM_CPH(1, 1, Ab, 2048, Bb, 2048);
    int st = 0;
    for (int i = 0; i < NBLK; i++){
        CP_WAIT(1);
        __syncthreads();
        if (i + 2 < NBLK){
            int st2 = st + 2; if (st2 >= 3) st2 -= 3;
            GEMM_CPH(i+2, st2, Ab, 2048, Bb, 2048);
        }
        compute64h(sbase + st*TILE_B, sbase + (3+st)*TILE_B, RA, RB, TA, TB, acc);
        if (++st == 3) st = 0;
    }

    #pragma unroll
    for (int mi = 0; mi < 2; mi++){
        int r0 = warp_m + mi*16 + lg;
        #pragma unroll
        for (int ni = 0; ni < 8; ni++){
            int h = nt*128 + warp_n + ni*8 + lk*2;
            float b0 = bsel[h], b1 = bsel[h+1];
            Outh[((size_t)r0*(NB*HD) + (size_t)bt*HD + h) >> 1] =
                pack_h2(acc[mi][ni][0]+b0, acc[mi][ni][1]+b1);
            Outh[((size_t)(r0+8)*(NB*HD) + (size_t)bt*HD + h) >> 1] =
                pack_h2(acc[mi][ni][2]+b0, acc[mi][ni][3]+b1);
        }
    }
}

// ---------------- K2: softmax ----------------
__global__ void k_softmax(){
    int bt = blockIdx.x, t = threadIdx.x;
    float v = g_Glogit[bt*NS + t];
    __shared__ float sm_[4], ss[4];
    float mx = v;
    #pragma unroll
    for (int o = 16; o; o >>= 1) mx = fmaxf(mx, __shfl_xor_sync(0xffffffffu, mx, o));
    if ((t & 31) == 0) sm_[t >> 5] = mx;
    __syncthreads();
    mx = fmaxf(fmaxf(sm_[0], sm_[1]), fmaxf(sm_[2], sm_[3]));
    float e = __expf(v - mx);
    float sum = e;
    #pragma unroll
    for (int o = 16; o; o >>= 1) sum += __shfl_xor_sync(0xffffffffu, sum, o);
    if ((t & 31) == 0) ss[t >> 5] = sum;
    __syncthreads();
    sum = ss[0] + ss[1] + ss[2] + ss[3];
    g_Gt[t*NB + bt] = e / sum;
}

// ---------------- K4: persistent scan (release-store arrival) ----------------
__device__ __forceinline__ void gsync(unsigned step, int tid, int cta){
    __syncthreads();
    if (tid == 0) st_release(&g_flags[cta*32], step);   // release orders prior writes
    if (tid < NCTA_SCAN){
        while (ldcg_u32(&g_flags[tid*32]) < step) { }
    }
    __threadfence();                                    // acquire side
    __syncthreads();
}
__device__ __forceinline__ float gru_upd(float fr, float fw, float y1, float y2,
                                         float b_ur, float b_u, float c, float g){
    float r  = 1.f / (1.f + __expf(-(fr + y1 + b_ur)));
    float ht = tanhf(fw + r * (y2 + b_u));
    return g * ht + (1.f - g) * c;
}

__global__ void __launch_bounds__(256,1) kF_scan(
        const float* __restrict__ bur, const float* __restrict__ bu){
    extern __shared__ unsigned us[];   // A subs: 4 x TILE_B; B resident: 4 x TILE_S at 4*TILE_B
    uint32_t sbase = smem_u32(us);
    int cta = blockIdx.x, tid = threadIdx.x;
    int wid = tid >> 5, lane = tid & 31, lg = lane >> 2, lk = lane & 3;
    int warp_m = (wid & 3) * 32, warp_n = (wid >> 2) * 32;
    int u16 = (tid & 7) * 16, rb = tid >> 3;
    uint32_t swz16 = (uint32_t)(((tid & 7) ^ (rb & 7)) * 16);
    LDSM_OFFSETS_H64();
    int nt  = cta >> 2;             // 0..31: 0-15 Y1 (Ur), 16-31 Y2 (U)
    int knt = cta & 3;              // K slice
    int kcb = knt * 256;            // K base (halves)
    const unsigned* Wsel = (nt < 16) ? g_Urh : g_Uh;
    int nbase = (nt & 15) * 64;
    unsigned* P = g_parth + (size_t)cta * 4096;   // 128x64 halves
    const char* Wb = reinterpret_cast<const char*>(Wsel) + (size_t)nbase*2048 + kcb*2;
    const char* Cb = reinterpret_cast<const char*>(g_Ch) + kcb*2;
    uint32_t bBase0 = sbase + 4*TILE_B;

    // resident fp16 weights: 4 chunks of 64 rows x 64 K
    #pragma unroll
    for (int j = 0; j < 8; j++){
        int c = j >> 1, n = rb + (j & 1)*32;
        cpa16(bBase0 + c*TILE_S + n*128 + swz16,
              Wb + (size_t)n*2048 + c*128 + u16);
    }
    CP_COMMIT();
    CP_WAIT(0);
    __syncthreads();

    int e  = (cta*256 + tid) * 4;   // 4 consecutive h per thread
    int eb = e >> 10, eh = e & (HD-1);
    int nt1 = eh >> 6, hm = eh & 63;
    float4 vur = *reinterpret_cast<const float4*>(bur + eh);
    float4 vu  = *reinterpret_cast<const float4*>(bu + eh);
    float4 creg = make_float4(0.f, 0.f, 0.f, 0.f);

    unsigned bar = 0;
    for (int s = 0; s < NS; s++){
        size_t fi = (((size_t)s*NB + eb)*HD + eh) >> 1;
        uint2 fru = *reinterpret_cast<const uint2*>(g_FRh + fi);
        uint2 fwu = *reinterpret_cast<const uint2*>(g_FWh + fi);
        float gg = g_Gt[s*NB + eb];

        // phase A: C slice (fp16), 4 sub-tiles of 64K, resident weights
        #pragma unroll
        for (int sg = 0; sg < 4; sg++){
            #pragma unroll
            for (int j = 0; j < 4; j++){
                int r = rb + j*32;
                cpa16(sbase + sg*TILE_B + r*128 + swz16,
                      Cb + (size_t)r*2048 + sg*128 + u16);
            }
            CP_COMMIT();
        }
        float acc[2][4][4]; ZERO_ACC4(acc);
        #pragma unroll
        for (int sub = 0; sub < 4; sub++){
            if (sub == 0)      CP_WAIT(3);
            else if (sub == 1) CP_WAIT(2);
            else if (sub == 2) CP_WAIT(1);
            else               CP_WAIT(0);
            __syncthreads();
            compute64h64(sbase + sub*TILE_B, bBase0 + sub*TILE_S, RA, RB, TA, TB, acc);
        }
        #pragma unroll
        for (int mi = 0; mi < 2; mi++){
            int r0 = warp_m + mi*16 + lg;
            #pragma unroll
            for (int ni = 0; ni < 4; ni++){
                int c2 = (warp_n + ni*8) / 2 + lk;
                stcg_u32(&P[r0*32 + c2],     pack_h2(acc[mi][ni][0], acc[mi][ni][1]));
                stcg_u32(&P[(r0+8)*32 + c2], pack_h2(acc[mi][ni][2], acc[mi][ni][3]));
            }
        }
        gsync(++bar, tid, cta);

        // phase B: reduce 4 fp16 partials per y, GRU update
        float2 y1a = make_float2(0,0), y1b = make_float2(0,0);
        float2 y2a = make_float2(0,0), y2b = make_float2(0,0);
        int pidx = eb*32 + (hm >> 1);
        #pragma unroll
        for (int kk = 0; kk < 4; kk++){
            uint2 p1 = *reinterpret_cast<const uint2*>(
                g_parth + (size_t)(nt1*4 + kk)*4096 + pidx);
            uint2 p2 = *reinterpret_cast<const uint2*>(
                g_parth + (size_t)((nt1+16)*4 + kk)*4096 + pidx);
            float2 a = h2f2(p1.x), b = h2f2(p1.y);
            y1a.x += a.x; y1a.y += a.y; y1b.x += b.x; y1b.y += b.y;
            float2 c = h2f2(p2.x), d = h2f2(p2.y);
            y2a.x += c.x; y2a.y += c.y; y2b.x += d.x; y2b.y += d.y;
        }
        float2 fr0 = h2f2(fru.x), fr1 = h2f2(fru.y);
        float2 fw0 = h2f2(fwu.x), fw1 = h2f2(fwu.y);
        creg.x = gru_upd(fr0.x, fw0.x, y1a.x, y2a.x, vur.x, vu.x, creg.x, gg);
        creg.y = gru_upd(fr0.y, fw0.y, y1a.y, y2a.y, vur.y, vu.y, creg.y, gg);
        creg.z = gru_upd(fr1.x, fw1.x, y1b.x, y2b.x, vur.z, vu.z, creg.z, gg);
        creg.w = gru_upd(fr1.y, fw1.y, y1b.y, y2b.y, vur.w, vu.w, creg.w, gg);
        __stcg(reinterpret_cast<uint2*>(g_Ch + (e >> 1)),
               make_uint2(pack_h2(creg.x, creg.y), pack_h2(creg.z, creg.w)));
        gsync(++bar, tid, cta);
    }
}

// ---------------- K5: final GEMM (pipelined split-K) ----------------
__global__ void __launch_bounds__(256,2) kF_out(){
    extern __shared__ unsigned us[];
    uint32_t sbase = smem_u32(us);
    int tid = threadIdx.x, wid = tid >> 5, lane = tid & 31;
    int lg = lane >> 2, lk = lane & 3;
    int warp_m = (wid >> 1) * 32, warp_n = (wid & 1) * 64;
    int nt = blockIdx.x, ks = blockIdx.y;
    int u16 = (tid & 7) * 16, rb = tid >> 3;
    uint32_t swz16 = (uint32_t)(((tid & 7) ^ (rb & 7)) * 16);
    LDSM_OFFSETS_H();
    int seg = ks >> 2;
    const unsigned* Asel = (seg == 0) ? g_pmh : (seg == 1 ? g_Ch : g_qh);
    const char* Ab = reinterpret_cast<const char*>(Asel) + (ks & 3) * 512;
    const char* Bb = reinterpret_cast<const char*>(g_Wmh) + (size_t)(nt*128)*6144 + ks*512;
    float acc[2][8][4]; ZERO_ACC(acc);

    const int NBLK = 4;
    GEMM_CPH(0, 0, Ab, 2048, Bb, 6144);
    GEMM_CPH(1, 1, Ab, 2048, Bb, 6144);
    int st = 0;
    for (int i = 0; i < NBLK; i++){
        CP_WAIT(1);
        __syncthreads();
        if (i + 2 < NBLK){
            int st2 = st + 2; if (st2 >= 3) st2 -= 3;
            GEMM_CPH(i+2, st2, Ab, 2048, Bb, 6144);
        }
        compute64h(sbase + st*TILE_B, sbase + (3+st)*TILE_B, RA, RB, TA, TB, acc);
        if (++st == 3) st = 0;
    }
    #pragma unroll
    for (int mi = 0; mi < 2; mi++){
        int r0 = warp_m + mi*16 + lg;
        #pragma unroll
        for (int ni = 0; ni < 8; ni++){
            int h = nt*128 + warp_n + ni*8 + lk*2;
            atomicAdd(&g_Otmp[(size_t)r0*HD + h     ], acc[mi][ni][0]);
            atomicAdd(&g_Otmp[(size_t)r0*HD + h + 1 ], acc[mi][ni][1]);
            atomicAdd(&g_Otmp[(size_t)(r0+8)*HD + h    ], acc[mi][ni][2]);
            atomicAdd(&g_Otmp[(size_t)(r0+8)*HD + h + 1], acc[mi][ni][3]);
        }
    }
}

// ---------------- K6: bias + relu ----------------
__global__ void k_finish(const float* __restrict__ bm, float* __restrict__ out){
    int i = blockIdx.x * blockDim.x + threadIdx.x;
    if (i < NB*HD){
        float v = g_Otmp[i] + bm[i & (HD-1)];
        out[i] = fmaxf(v, 0.f);
    }
}

// ---------------- launch ----------------
extern "C" void kernel_launch(void* const* d_in, const int* in_sizes, int n_in,
                              void* d_out, int out_size){
    (void)in_sizes; (void)n_in; (void)out_size;
    const float* facts     = (const float*)d_in[0];
    const float* questions = (const float*)d_in[1];
    const float* prevM     = (const float*)d_in[2];
    const float* Wr  = (const float*)d_in[3];
    const float* br  = (const float*)d_in[4];
    const float* Ur  = (const float*)d_in[5];
    const float* bur = (const float*)d_in[6];
    const float* W   = (const float*)d_in[7];
    const float* bw  = (const float*)d_in[8];
    const float* U   = (const float*)d_in[9];
    const float* bu  = (const float*)d_in[10];
    const float* Wz1 = (const float*)d_in[11];
    const float* bz1 = (const float*)d_in[12];
    const float* Wz2 = (const float*)d_in[13];
    const float* Wm  = (const float*)d_in[15];
    const float* bm  = (const float*)d_in[16];
    float* out = (float*)d_out;

    static int attr_done = 0;
    if (!attr_done){
        cudaFuncSetAttribute(kF_G,    cudaFuncAttributeMaxDynamicSharedMemorySize, GEMM_SMEM);
        cudaFuncSetAttribute(kF_F,    cudaFuncAttributeMaxDynamicSharedMemorySize, GEMM_SMEM);
        cudaFuncSetAttribute(kF_scan, cudaFuncAttributeMaxDynamicSharedMemorySize, SCAN_SMEM);
        cudaFuncSetAttribute(kF_out,  cudaFuncAttributeMaxDynamicSharedMemorySize, GEMM_SMEM);
        attr_done = 1;
    }

    unsigned *dWz1h, *dWrh, *dWh, *dUrh, *dUh, *dWmh, *dpmh, *dqh;
    cudaGetSymbolAddress((void**)&dWz1h, g_Wz1h);
    cudaGetSymbolAddress((void**)&dWrh,  g_Wrh);
    cudaGetSymbolAddress((void**)&dWh,   g_Wh);
    cudaGetSymbolAddress((void**)&dUrh,  g_Urh);
    cudaGetSymbolAddress((void**)&dUh,   g_Uh);
    cudaGetSymbolAddress((void**)&dWmh,  g_Wmh);
    cudaGetSymbolAddress((void**)&dpmh,  g_pmh);
    cudaGetSymbolAddress((void**)&dqh,   g_qh);

    k_init<<<512, 256>>>();
    k_zb_h<<<NROW, 256>>>(facts, questions, prevM);       // also emits g_fh
    k_cvt_h<<<1024, 256>>>((const float4*)Wz1, (uint2*)dWz1h, (HD*4*HD)/4);
    dim3 g4(512, 4);
    k_cvt4<<<g4, 256>>>((const float4*)Wr, (const float4*)W,
                        (const float4*)Ur, (const float4*)U,
                        (uint2*)dWrh, (uint2*)dWh, (uint2*)dUrh, (uint2*)dUh, (HD*HD)/4);
    k_cvt_h<<<1024, 256>>>((const float4*)Wm, (uint2*)dWmh, (HD*3*HD)/4);
    dim3 g2(128, 2);
    k_cvt4<<<g2, 256>>>((const float4*)prevM, (const float4*)questions,
                        (const float4*)prevM, (const float4*)questions,
                        (uint2*)dpmh, (uint2*)dqh, (uint2*)dpmh, (uint2*)dqh, (NB*HD)/4);
    dim3 gG(8, 128);
    kF_G<<<gG, 256, GEMM_SMEM>>>(bz1, Wz2);
    k_softmax<<<128, 128>>>();
    dim3 gF(8, 128, 2);
    kF_F<<<gF, 256, GEMM_SMEM>>>(br, bw);
    kF_scan<<<NCTA_SCAN, 256, SCAN_SMEM>>>(bur, bu);
    dim3 gO(8, 12);
    kF_out<<<gO, 256, GEMM_SMEM>>>();
    k_finish<<<512, 256>>>(bm, out);
}